// round 17
// baseline (speedup 1.0000x reference)
#include <cuda_runtime.h>
#include <cuda_fp16.h>
#include <cuda_bf16.h>
#include <math.h>
#include <stdint.h>

#define D     128
#define NMAX  50000
#define EMAX  800000
#define NPAD  (NMAX + 128)
#define PS    68          // padded smem row stride (words)

// ---- scratch (device globals; zero at load) ----
__device__ __align__(16) __half   g_T16[NPAD * D];      // message table (fp16, prescaled)
__device__ __align__(16) uint32_t g_Xh[NPAD * 64];      // split input hi pairs (also A)
__device__ __align__(16) uint32_t g_Xl[NPAD * 64];      // split input lo pairs
__device__ __align__(16) uint32_t g_Whi[2 * 8192];      // packed W hi, [m][n][kp]
__device__ __align__(16) uint32_t g_Wlo[2 * 8192];
__device__ __align__(16) int g_cntPos[NMAX];   // atomic counters; 0 on entry (K3 re-zeroes)
__device__ __align__(16) int g_cnt[NMAX];      // indeg
__device__ __align__(16) int g_rowptr[NMAX];
__device__ int   g_rank[EMAX];                 // within-destination rank
__device__ int   g_eidx[EMAX];                 // CSR source indices
__device__ float g_dinv[NMAX];
__device__ __align__(16) float g_gate[D];
__device__ __align__(16) float g_hbias[D];

// ---------------------------------------------------------------- helpers
__device__ __forceinline__ void split2f(float a, float b, uint32_t& hi, uint32_t& lo) {
    asm("cvt.rn.bf16x2.f32 %0, %1, %2;" : "=r"(hi) : "f"(b), "f"(a));
    float ha = __uint_as_float(hi << 16);
    float hb = __uint_as_float(hi & 0xffff0000u);
    float la = a - ha;
    float lb = b - hb;
    asm("cvt.rn.bf16x2.f32 %0, %1, %2;" : "=r"(lo) : "f"(lb), "f"(la));
}
__device__ __forceinline__ __half2 h2(uint32_t u) { return *(__half2*)&u; }

// ---------------------------------------------------------------- K1: const + split + count/rank
__global__ void k_pre(const float* __restrict__ W1, const float* __restrict__ W2,
                      const float* __restrict__ ctx, const float* __restrict__ Wg,
                      const float* __restrict__ bg,  const float* __restrict__ Wb,
                      const float* __restrict__ X,
                      const int* __restrict__ edst,
                      int n, int E, int nbS) {
    int blk = blockIdx.x;
    int tid = threadIdx.x;
    if (blk < 64) {                                     // W split/pack/transpose
        int idx = blk * 256 + tid;                      // 0..16383
        int m  = idx >> 13;
        int r  = idx & 8191;
        int nn = r & 127;
        int kp = r >> 7;
        const float* W = m ? W2 : W1;
        float w0 = W[(2 * kp) * D + nn];
        float w1 = W[(2 * kp + 1) * D + nn];
        uint32_t hi, lo;
        split2f(w0, w1, hi, lo);
        g_Whi[m * 8192 + nn * 64 + kp] = hi;
        g_Wlo[m * 8192 + nn * 64 + kp] = lo;
    } else if (blk < 80) {                              // hypernet
        int w    = (blk - 64) * 8 + (tid >> 5);
        int lane = tid & 31;
        float c0 = ctx[lane], c1 = ctx[lane + 32];
        float g = c0 * Wg[lane * D + w] + c1 * Wg[(lane + 32) * D + w];
        float b = c0 * Wb[lane * D + w] + c1 * Wb[(lane + 32) * D + w];
#pragma unroll
        for (int o = 16; o > 0; o >>= 1) {
            g += __shfl_down_sync(0xffffffffu, g, o);
            b += __shfl_down_sync(0xffffffffu, b, o);
        }
        if (lane == 0) {
            g_gate[w]  = 1.f / (1.f + __expf(-(g + bg[w])));
            g_hbias[w] = b;
        }
    } else if (blk < 80 + nbS) {                        // input split
        int i = (blk - 80) * 256 + tid;                 // float4 index
        if (i >= n * 32) return;
        float4 v = ((const float4*)X)[i];
        int row = i >> 5, c4 = i & 31;
        uint32_t h01, l01, h23, l23;
        split2f(v.x, v.y, h01, l01);
        split2f(v.z, v.w, h23, l23);
        *((uint2*)&g_Xh[(size_t)row * 64 + c4 * 2]) = make_uint2(h01, h23);
        *((uint2*)&g_Xl[(size_t)row * 64 + c4 * 2]) = make_uint2(l01, l23);
    } else {                                            // edge count + rank
        int i = (blk - 80 - nbS) * 256 + tid;
        if (i >= E) return;
        int d = edst[i];
        if ((unsigned)d < (unsigned)n)
            g_rank[i] = atomicAdd(&g_cntPos[d], 1);
    }
}

// ---------------------------------------------------------------- GEMM body (bf16x3 MMA, fp16 out)
__device__ __forceinline__ void mma16816(float* c, uint32_t a0, uint32_t a1,
                                         uint32_t a2, uint32_t a3,
                                         uint32_t b0, uint32_t b1) {
    asm volatile("mma.sync.aligned.m16n8k16.row.col.f32.bf16.bf16.f32 "
                 "{%0,%1,%2,%3}, {%4,%5,%6,%7}, {%8,%9}, {%0,%1,%2,%3};"
                 : "+f"(c[0]), "+f"(c[1]), "+f"(c[2]), "+f"(c[3])
                 : "r"(a0), "r"(a1), "r"(a2), "r"(a3), "r"(b0), "r"(b1));
}

// dmode 0: dinv computed inline from g_cntPos (conv1; counters read-only during K2)
// dmode 1: dinv from g_dinv (conv2)
__device__ void gemm_body(uint32_t* sm, int r0, int wsel, int dmode, int n) {
    uint32_t* Xh = sm;
    uint32_t* Xl = Xh + 128 * PS;
    uint32_t* Wh = Xl + 128 * PS;
    uint32_t* Wl = Wh + 128 * PS;
    int tid = threadIdx.x;

    const uint32_t* gwh = g_Whi + wsel * 8192;
    const uint32_t* gwl = g_Wlo + wsel * 8192;
#pragma unroll
    for (int i = 0; i < 8; i++) {
        int q  = tid + i * 256;
        int wb = q * 4;
        int nn = wb >> 6, kp = wb & 63;
        *((uint4*)&Wh[nn * PS + kp]) = ((const uint4*)gwh)[q];
        *((uint4*)&Wl[nn * PS + kp]) = ((const uint4*)gwl)[q];
    }
    const uint4* gxh = (const uint4*)g_Xh + (size_t)r0 * 16;
    const uint4* gxl = (const uint4*)g_Xl + (size_t)r0 * 16;
#pragma unroll
    for (int i = 0; i < 8; i++) {
        int q   = tid + i * 256;
        int row = q >> 4, k4 = q & 15;
        *((uint4*)&Xh[row * PS + k4 * 4]) = gxh[q];
        *((uint4*)&Xl[row * PS + k4 * 4]) = gxl[q];
    }
    __syncthreads();

    int wid  = tid >> 5;
    int lane = tid & 31;
    int g    = lane >> 2;
    int tig  = lane & 3;
    int rA   = wid * 16 + g;

    float acc[16][4];
#pragma unroll
    for (int t = 0; t < 16; t++)
#pragma unroll
        for (int c = 0; c < 4; c++) acc[t][c] = 0.f;

#pragma unroll
    for (int s = 0; s < 8; s++) {
        int kp = s * 8;
        uint32_t ah0 = Xh[rA * PS + kp + tig];
        uint32_t ah1 = Xh[(rA + 8) * PS + kp + tig];
        uint32_t ah2 = Xh[rA * PS + kp + tig + 4];
        uint32_t ah3 = Xh[(rA + 8) * PS + kp + tig + 4];
        uint32_t al0 = Xl[rA * PS + kp + tig];
        uint32_t al1 = Xl[(rA + 8) * PS + kp + tig];
        uint32_t al2 = Xl[rA * PS + kp + tig + 4];
        uint32_t al3 = Xl[(rA + 8) * PS + kp + tig + 4];
#pragma unroll
        for (int nt = 0; nt < 16; nt++) {
            int nb = nt * 8 + g;
            uint32_t bh0 = Wh[nb * PS + kp + tig];
            uint32_t bh1 = Wh[nb * PS + kp + tig + 4];
            uint32_t bl0 = Wl[nb * PS + kp + tig];
            uint32_t bl1 = Wl[nb * PS + kp + tig + 4];
            mma16816(acc[nt], ah0, ah1, ah2, ah3, bh0, bh1);
            mma16816(acc[nt], ah0, ah1, ah2, ah3, bl0, bl1);
            mma16816(acc[nt], al0, al1, al2, al3, bh0, bh1);
        }
    }

    int gr0 = r0 + wid * 16 + g;
    int gr1 = gr0 + 8;
    float d0 = 0.f, d1 = 0.f;
    if (dmode == 0) {
        if (gr0 < n) d0 = rsqrtf((float)(g_cntPos[gr0] + 1));
        if (gr1 < n) d1 = rsqrtf((float)(g_cntPos[gr1] + 1));
    } else {
        if (gr0 < n) d0 = g_dinv[gr0];
        if (gr1 < n) d1 = g_dinv[gr1];
    }
#pragma unroll
    for (int nt = 0; nt < 16; nt++) {
        int c = nt * 8 + 2 * tig;
        if (gr0 < n)
            *((__half2*)&g_T16[(size_t)gr0 * D + c]) =
                __floats2half2_rn(acc[nt][0] * d0, acc[nt][1] * d0);
        if (gr1 < n)
            *((__half2*)&g_T16[(size_t)gr1 * D + c]) =
                __floats2half2_rn(acc[nt][2] * d1, acc[nt][3] * d1);
    }
}

// ---------------------------------------------------------------- K2: rowptr-only scan (block 0) || GEMM1
__global__ void __launch_bounds__(256)
k_scan_gemm(int n) {
    extern __shared__ uint32_t sm[];
    if (blockIdx.x != 0) {
        gemm_body(sm, (blockIdx.x - 1) * 128, 0, /*dmode=*/0, n);
        return;
    }
    __shared__ int part[256];
    int tid = threadIdx.x;
    const int per = 196;                    // 256*196 >= 50000, %4==0
    int base = tid * per;
    int s = 0;
    for (int i = 0; i < per; i += 4) {
        int r = base + i;
        if (r + 3 < n) {
            int4 v = *((const int4*)&g_cntPos[r]);
            s += v.x + v.y + v.z + v.w;
        } else {
#pragma unroll
            for (int u = 0; u < 4; u++)
                if (r + u < n) s += g_cntPos[r + u];
        }
    }
    part[tid] = s;
    __syncthreads();
    for (int off = 1; off < 256; off <<= 1) {
        int v = (tid >= off) ? part[tid - off] : 0;
        __syncthreads();
        part[tid] += v;
        __syncthreads();
    }
    int run = (tid == 0) ? 0 : part[tid - 1];
    for (int i = 0; i < per; i += 4) {
        int r = base + i;
        if (r >= n) break;
        if (r + 3 < n) {
            int4 v = *((const int4*)&g_cntPos[r]);
            int4 rp;
            rp.x = run;
            rp.y = rp.x + v.x;
            rp.z = rp.y + v.y;
            rp.w = rp.z + v.z;
            run  = rp.w + v.w;
            *((int4*)&g_rowptr[r]) = rp;
        } else {
#pragma unroll
            for (int u = 0; u < 4; u++) {
                int rr = r + u;
                if (rr < n) {
                    g_rowptr[rr] = run;
                    run += g_cntPos[rr];
                }
            }
        }
    }
}

// ---------------------------------------------------------------- standalone GEMM (conv2)
__global__ void __launch_bounds__(256)
k_gemm(int wsel, int n) {
    extern __shared__ uint32_t sm[];
    gemm_body(sm, blockIdx.x * 128, wsel, /*dmode=*/1, n);
}

// ---------------------------------------------------------------- K3: CSR place || node finalize
__global__ void k_place_fin(const int* __restrict__ esrc,
                            const int* __restrict__ edst,
                            int E, int n, int nbE) {
    int blk = blockIdx.x;
    int tid = threadIdx.x;
    if (blk < nbE) {
        int i = blk * 256 + tid;
        if (i >= E) return;
        int s = esrc[i];
        int d = edst[i];
        if ((unsigned)s >= (unsigned)n || (unsigned)d >= (unsigned)n) return;
        g_eidx[g_rowptr[d] + g_rank[i]] = s;
    } else {
        int i = (blk - nbE) * 256 + tid;
        if (i < n) {
            int c = g_cntPos[i];
            g_cnt[i]  = c;
            g_dinv[i] = rsqrtf((float)(c + 1));
            g_cntPos[i] = 0;                // restore invariant for next call
        }
    }
}

// ---------------------------------------------------------------- fused gather + epilogue (fp16 T)
// HALF-WARP per row; 8-deep load pipeline (MLP 8) with depth-3 HADD2 trees.
// T rows prescaled by dinv[src]: out[d] = epi( dinv[d] * sum_{s in d+in(d)} T[s] + b )
template <int MODE>
__global__ void __launch_bounds__(256, 5)
k_gather(float* __restrict__ Out, const float* __restrict__ bvec, int n) {
    int gtid = blockIdx.x * blockDim.x + threadIdx.x;
    int w = gtid >> 4;                      // half-warp id = row
    if (w >= n) return;
    int lane16 = threadIdx.x & 15;
    unsigned hmask = (threadIdx.x & 16) ? 0xffff0000u : 0x0000ffffu;

    int beg = g_rowptr[w];
    int cnt = g_cnt[w];
    const char* base = (const char*)g_T16 + lane16 * 16;   // per-lane 16B column slice

    float a0, a1, a2, a3, a4, a5, a6, a7;
    {   // self term
        uint4 sv = *(const uint4*)(base + ((unsigned)w << 8));
        float2 f0 = __half22float2(h2(sv.x));
        float2 f1 = __half22float2(h2(sv.y));
        float2 f2 = __half22float2(h2(sv.z));
        float2 f3 = __half22float2(h2(sv.w));
        a0 = f0.x; a1 = f0.y; a2 = f1.x; a3 = f1.y;
        a4 = f2.x; a5 = f2.y; a6 = f3.x; a7 = f3.y;
    }

    int j = 0;
    while (j < cnt) {
        int chunk = min(cnt - j, 16);
        unsigned myoff = 0;
        if (lane16 < chunk) myoff = (unsigned)g_eidx[beg + j + lane16] << 8;
        int t = 0;
        for (; t + 7 < chunk; t += 8) {     // MLP-8 fast path (avg degree 16 -> 2 iters)
            unsigned o0 = __shfl_sync(hmask, myoff, t,     16);
            unsigned o1 = __shfl_sync(hmask, myoff, t + 1, 16);
            unsigned o2 = __shfl_sync(hmask, myoff, t + 2, 16);
            unsigned o3 = __shfl_sync(hmask, myoff, t + 3, 16);
            unsigned o4 = __shfl_sync(hmask, myoff, t + 4, 16);
            unsigned o5 = __shfl_sync(hmask, myoff, t + 5, 16);
            unsigned o6 = __shfl_sync(hmask, myoff, t + 6, 16);
            unsigned o7 = __shfl_sync(hmask, myoff, t + 7, 16);
            uint4 v0 = *(const uint4*)(base + o0);
            uint4 v1 = *(const uint4*)(base + o1);
            uint4 v2 = *(const uint4*)(base + o2);
            uint4 v3 = *(const uint4*)(base + o3);
            uint4 v4 = *(const uint4*)(base + o4);
            uint4 v5 = *(const uint4*)(base + o5);
            uint4 v6 = *(const uint4*)(base + o6);
            uint4 v7 = *(const uint4*)(base + o7);
            __half2 s0 = __hadd2(__hadd2(__hadd2(h2(v0.x), h2(v1.x)), __hadd2(h2(v2.x), h2(v3.x))),
                                 __hadd2(__hadd2(h2(v4.x), h2(v5.x)), __hadd2(h2(v6.x), h2(v7.x))));
            __half2 s1 = __hadd2(__hadd2(__hadd2(h2(v0.y), h2(v1.y)), __hadd2(h2(v2.y), h2(v3.y))),
                                 __hadd2(__hadd2(h2(v4.y), h2(v5.y)), __hadd2(h2(v6.y), h2(v7.y))));
            __half2 s2 = __hadd2(__hadd2(__hadd2(h2(v0.z), h2(v1.z)), __hadd2(h2(v2.z), h2(v3.z))),
                                 __hadd2(__hadd2(h2(v4.z), h2(v5.z)), __hadd2(h2(v6.z), h2(v7.z))));
            __half2 s3 = __hadd2(__hadd2(__hadd2(h2(v0.w), h2(v1.w)), __hadd2(h2(v2.w), h2(v3.w))),
                                 __hadd2(__hadd2(h2(v4.w), h2(v5.w)), __hadd2(h2(v6.w), h2(v7.w))));
            float2 f0 = __half22float2(s0);
            float2 f1 = __half22float2(s1);
            float2 f2 = __half22float2(s2);
            float2 f3 = __half22float2(s3);
            a0 += f0.x; a1 += f0.y; a2 += f1.x; a3 += f1.y;
            a4 += f2.x; a5 += f2.y; a6 += f3.x; a7 += f3.y;
        }
        for (; t + 3 < chunk; t += 4) {
            unsigned o0 = __shfl_sync(hmask, myoff, t,     16);
            unsigned o1 = __shfl_sync(hmask, myoff, t + 1, 16);
            unsigned o2 = __shfl_sync(hmask, myoff, t + 2, 16);
            unsigned o3 = __shfl_sync(hmask, myoff, t + 3, 16);
            uint4 v0 = *(const uint4*)(base + o0);
            uint4 v1 = *(const uint4*)(base + o1);
            uint4 v2 = *(const uint4*)(base + o2);
            uint4 v3 = *(const uint4*)(base + o3);
            __half2 s0 = __hadd2(__hadd2(h2(v0.x), h2(v1.x)), __hadd2(h2(v2.x), h2(v3.x)));
            __half2 s1 = __hadd2(__hadd2(h2(v0.y), h2(v1.y)), __hadd2(h2(v2.y), h2(v3.y)));
            __half2 s2 = __hadd2(__hadd2(h2(v0.z), h2(v1.z)), __hadd2(h2(v2.z), h2(v3.z)));
            __half2 s3 = __hadd2(__hadd2(h2(v0.w), h2(v1.w)), __hadd2(h2(v2.w), h2(v3.w)));
            float2 f0 = __half22float2(s0);
            float2 f1 = __half22float2(s1);
            float2 f2 = __half22float2(s2);
            float2 f3 = __half22float2(s3);
            a0 += f0.x; a1 += f0.y; a2 += f1.x; a3 += f1.y;
            a4 += f2.x; a5 += f2.y; a6 += f3.x; a7 += f3.y;
        }
        for (; t < chunk; t++) {
            unsigned o = __shfl_sync(hmask, myoff, t, 16);
            uint4 v = *(const uint4*)(base + o);
            float2 f0 = __half22float2(h2(v.x));
            float2 f1 = __half22float2(h2(v.y));
            float2 f2 = __half22float2(h2(v.z));
            float2 f3 = __half22float2(h2(v.w));
            a0 += f0.x; a1 += f0.y; a2 += f1.x; a3 += f1.y;
            a4 += f2.x; a5 += f2.y; a6 += f3.x; a7 += f3.y;
        }
        j += chunk;
    }

    float di = g_dinv[w];
    float4 bA = ((const float4*)bvec)[lane16 * 2];
    float4 bB = ((const float4*)bvec)[lane16 * 2 + 1];
    float o0 = a0 * di + bA.x;
    float o1 = a1 * di + bA.y;
    float o2 = a2 * di + bA.z;
    float o3 = a3 * di + bA.w;
    float o4 = a4 * di + bB.x;
    float o5 = a5 * di + bB.y;
    float o6 = a6 * di + bB.z;
    float o7 = a7 * di + bB.w;
    if (MODE == 1) {
        o0 = o0 > 0.f ? o0 : 0.2f * o0;
        o1 = o1 > 0.f ? o1 : 0.2f * o1;
        o2 = o2 > 0.f ? o2 : 0.2f * o2;
        o3 = o3 > 0.f ? o3 : 0.2f * o3;
        o4 = o4 > 0.f ? o4 : 0.2f * o4;
        o5 = o5 > 0.f ? o5 : 0.2f * o5;
        o6 = o6 > 0.f ? o6 : 0.2f * o6;
        o7 = o7 > 0.f ? o7 : 0.2f * o7;
        uint32_t h01, l01, h23, l23, h45, l45, h67, l67;
        split2f(o0, o1, h01, l01);
        split2f(o2, o3, h23, l23);
        split2f(o4, o5, h45, l45);
        split2f(o6, o7, h67, l67);
        *((uint4*)&g_Xh[(size_t)w * 64 + lane16 * 4]) = make_uint4(h01, h23, h45, h67);
        *((uint4*)&g_Xl[(size_t)w * 64 + lane16 * 4]) = make_uint4(l01, l23, l45, l67);
    } else {
        float4 gA = ((const float4*)g_gate)[lane16 * 2];
        float4 gB = ((const float4*)g_gate)[lane16 * 2 + 1];
        float4 hA = ((const float4*)g_hbias)[lane16 * 2];
        float4 hB = ((const float4*)g_hbias)[lane16 * 2 + 1];
        float4 r0 = make_float4(o0 * gA.x + hA.x, o1 * gA.y + hA.y,
                                o2 * gA.z + hA.z, o3 * gA.w + hA.w);
        float4 r1 = make_float4(o4 * gB.x + hB.x, o5 * gB.y + hB.y,
                                o6 * gB.z + hB.z, o7 * gB.w + hB.w);
        ((float4*)(Out + (size_t)w * D))[lane16 * 2]     = r0;
        ((float4*)(Out + (size_t)w * D))[lane16 * 2 + 1] = r1;
    }
}

// ----------------------------------------------------------------
extern "C" void kernel_launch(void* const* d_in, const int* in_sizes, int n_in,
                              void* d_out, int out_size) {
    const float* x    = (const float*)d_in[0];
    const float* ctx  = (const float*)d_in[1];
    const float* W1   = (const float*)d_in[2];
    const float* b1   = (const float*)d_in[3];
    const float* W2   = (const float*)d_in[4];
    const float* b2   = (const float*)d_in[5];
    const float* Wg   = (const float*)d_in[6];
    const float* bg   = (const float*)d_in[7];
    const float* Wb   = (const float*)d_in[8];
    const int*   ei   = (const int*)d_in[9];     // int32 (JAX x64 disabled)
    float*       out  = (float*)d_out;

    int N = in_sizes[0] / D;
    int E = in_sizes[9] / 2;
    const int* esrc = ei;
    const int* edst = ei + E;

    int smemG = 4 * 128 * PS * sizeof(uint32_t);          // 139264 B
    cudaFuncSetAttribute(k_scan_gemm,
                         cudaFuncAttributeMaxDynamicSharedMemorySize, smemG);
    cudaFuncSetAttribute(k_gemm,
                         cudaFuncAttributeMaxDynamicSharedMemorySize, smemG);

    int nbS  = (N * 32 + 255) / 256;
    int nbE  = (E + 255) / 256;
    int nbN  = (N + 255) / 256;
    int gblk = (N + 127) / 128;
    long long gth = (long long)N * 16;            // one HALF-warp per node
    int nbG  = (int)((gth + 255) / 256);

    // K1: const + input split + edge count/rank
    k_pre<<<80 + nbS + nbE, 256>>>(W1, W2, ctx, Wg, bg, Wb, x, edst, N, E, nbS);

    // K2: rowptr scan (block 0, prefix-sum only) || GEMM1
    k_scan_gemm<<<1 + gblk, 256, smemG>>>(N);

    // K3: CSR place || node finalize (cnt/dinv/zero)
    k_place_fin<<<nbE + nbN, 256>>>(esrc, edst, E, N, nbE);

    // K4: conv1 gather -> A (split bf16)
    k_gather<1><<<nbG, 256>>>(nullptr, b1, N);

    // K5: GEMM2 (fp16 out, prescaled by g_dinv)
    k_gemm<<<gblk, 256, smemG>>>(1, N);

    // K6: conv2 gather -> out
    k_gather<2><<<nbG, 256>>>(out, b2, N);
}